// round 16
// baseline (speedup 1.0000x reference)
#include <cuda_runtime.h>
#include <cuda_fp16.h>
#include <cstdint>

// ---------------------------------------------------------------------------
// SpectralMSA channel attention — Round 16: fully weight-folded pipeline.
//   logits path (R15): G = x^T x (sym, tri+mirror), T = Wk G,
//                      logits = T Wq^T + fused softmax -> P.
//   output path (new): U_b[c,hd] = sum_e Wv[he,c] P_bh[d,e]  (fp32 FMA)
//                      W''_b = Wproj . U_b^T-ish (3-term mma)
//                      y_b   = x_b W''_b^T + bias (2-term mma)
//   v-projection, pv and GEMM3 are eliminated entirely.
// ---------------------------------------------------------------------------

namespace {
constexpr int kB = 4;
constexpr int kN = 4096;
constexpr int kC = 1024;
constexpr int kH = 16;
constexpr int kD = 64;
constexpr int kM = kB * kN;        // 16384
constexpr int kQKV = 3 * kC;       // 3072
}

// fp32 scratch
__device__ float g_attnP[(size_t)kB * kH * kD * kD];
// split-fp16 operands
__device__ __half g_xH[(size_t)kM * kC],       g_xL[(size_t)kM * kC];
__device__ __half g_xtH[(size_t)kB * kC * kN], g_xtL[(size_t)kB * kC * kN];
__device__ __half g_wqkvH[(size_t)kQKV * kC],  g_wqkvL[(size_t)kQKV * kC];
__device__ __half g_wprojH[(size_t)kC * kC],   g_wprojL[(size_t)kC * kC];
__device__ __half g_GH[(size_t)kB * kC * kC],  g_GL[(size_t)kB * kC * kC];
__device__ __half g_TH[(size_t)kB * kC * kC],  g_TL[(size_t)kB * kC * kC];
__device__ __half g_UtH[(size_t)kB * kC * kC], g_UtL[(size_t)kB * kC * kC];  // [b][c][hd]
__device__ __half g_W2H[(size_t)kB * kC * kC], g_W2L[(size_t)kB * kC * kC];  // [b][o][c]

// ---------------- low-level helpers ----------------------------------------
__device__ __forceinline__ void mma_f16_f32(float& d0, float& d1, float& d2, float& d3,
                                            unsigned a0, unsigned a1, unsigned a2, unsigned a3,
                                            unsigned b0, unsigned b1)
{
    asm volatile(
        "mma.sync.aligned.m16n8k16.row.col.f32.f16.f16.f32 "
        "{%0,%1,%2,%3},{%4,%5,%6,%7},{%8,%9},{%0,%1,%2,%3};"
        : "+f"(d0), "+f"(d1), "+f"(d2), "+f"(d3)
        : "r"(a0), "r"(a1), "r"(a2), "r"(a3), "r"(b0), "r"(b1));
}
__device__ __forceinline__ void split2pack_h(float a, float b, unsigned& h, unsigned& l)
{
    __half ha = __float2half_rn(a), hb = __float2half_rn(b);
    __half2 ph(ha, hb); h = *(unsigned*)&ph;
    __half2 pl(__float2half_rn(a - __half2float(ha)),
               __float2half_rn(b - __half2float(hb)));
    l = *(unsigned*)&pl;
}
__device__ __forceinline__ uint32_t smem_u32(const void* p) {
    uint32_t a;
    asm("{ .reg .u64 t; cvta.to.shared.u64 t, %1; cvt.u32.u64 %0, t; }"
        : "=r"(a) : "l"(p));
    return a;
}
__device__ __forceinline__ void cp16(uint32_t dst, const void* src) {
    asm volatile("cp.async.cg.shared.global [%0], [%1], 16;" :: "r"(dst), "l"(src));
}
__device__ __forceinline__ void cp_commit() {
    asm volatile("cp.async.commit_group;" ::: "memory");
}
template <int N>
__device__ __forceinline__ void cp_wait() {
    asm volatile("cp.async.wait_group %0;" :: "n"(N) : "memory");
}
__device__ __forceinline__ void ldsm4(unsigned* r, uint32_t addr) {
    asm volatile("ldmatrix.sync.aligned.m8n8.x4.shared.b16 {%0,%1,%2,%3}, [%4];"
                 : "=r"(r[0]), "=r"(r[1]), "=r"(r[2]), "=r"(r[3]) : "r"(addr));
}

// ---------------------------------------------------------------------------
__global__ void split_kernel(const float* __restrict__ src,
                             __half* __restrict__ hi,
                             __half* __restrict__ lo, int n4)
{
    int i = blockIdx.x * blockDim.x + threadIdx.x;
    if (i >= n4) return;
    float4 v = ((const float4*)src)[i];
    unsigned h0, h1, l0, l1;
    split2pack_h(v.x, v.y, h0, l0);
    split2pack_h(v.z, v.w, h1, l1);
    ((uint2*)hi)[i] = make_uint2(h0, h1);
    ((uint2*)lo)[i] = make_uint2(l0, l1);
}

// transpose + split: x [B*N, C] fp32 -> xt [B][C][N] fp16 hi/lo
__global__ __launch_bounds__(256)
void transpose_split_kernel(const float* __restrict__ x)
{
    __shared__ float s[32][33];
    const int c0 = blockIdx.x * 32;
    const int n0 = blockIdx.y * 32;
    const int t = threadIdx.x;
    const int tc = t & 31, tr = t >> 5;

#pragma unroll
    for (int i = 0; i < 4; ++i) {
        const int row = tr + i * 8;
        s[row][tc] = x[(size_t)(n0 + row) * kC + c0 + tc];
    }
    __syncthreads();

    const int b = n0 >> 12;
    const int nb = n0 & 4095;
#pragma unroll
    for (int i = 0; i < 4; ++i) {
        const int cc = tr + i * 8;
        const float v = s[tc][cc];
        __half hv = __float2half_rn(v);
        const size_t o = ((size_t)b * kC + c0 + cc) * kN + nb + tc;
        g_xtH[o] = hv;
        g_xtL[o] = __float2half_rn(v - __half2float(hv));
    }
}

// ---------------------------------------------------------------------------
// Unified fp16-split GEMM (NT): 3-stage k32 cp.async ring, XOR swizzle.
// MODE 0: fp32 C + bias (+ per-z batch offset). MODE 2: split fp16 out.
// NTERMS = 2 (HH+HL) or 3 (+LH).
// ---------------------------------------------------------------------------
namespace {
constexpr int ROWB   = 64;
constexpr int PLANE  = 128 * ROWB;       // 8192 B
constexpr int STAGEB = 4 * PLANE;        // 32768 B
constexpr int SMEM_GEMM = 3 * STAGEB;    // 98304 B
}

template <int MODE, int NTERMS>
__global__ __launch_bounds__(256)
void f16_gemm(const __half* __restrict__ AH, const __half* __restrict__ AL,
              const __half* __restrict__ BH, const __half* __restrict__ BL,
              float* __restrict__ C, const float* __restrict__ bias,
              __half* __restrict__ CH, __half* __restrict__ CL,
              int M, int N, int K,
              size_t aBatch, size_t bBatch, size_t cBatch)
{
    extern __shared__ char sm[];
    const uint32_t sbase = smem_u32(sm);

    const int z = blockIdx.z;
    AH += (size_t)z * aBatch; AL += (size_t)z * aBatch;
    BH += (size_t)z * bBatch; BL += (size_t)z * bBatch;

    const int t = threadIdx.x;
    const int warp = t >> 5, lane = t & 31;
    const int wm = (warp & 1) * 64;
    const int wn = (warp >> 1) * 32;
    const int m0 = blockIdx.y * 128, n0 = blockIdx.x * 128;

    const int lrowA = t >> 2, lcA = t & 3;
    const int lrowB = (t + 256) >> 2, lcB = (t + 256) & 3;
    const uint32_t dA = lrowA * ROWB + ((lcA ^ ((lrowA >> 1) & 3)) << 4);
    const uint32_t dB = lrowB * ROWB + ((lcB ^ ((lrowB >> 1) & 3)) << 4);

    const __half* pAH = AH + (size_t)m0 * K;
    const __half* pAL = AL + (size_t)m0 * K;
    const __half* pBH = BH + (size_t)n0 * K;
    const __half* pBL = BL + (size_t)n0 * K;

    auto load_stage = [&](uint32_t stoff, int k0) {
        const uint32_t s0 = sbase + stoff;
        const size_t gA = (size_t)lrowA * K + k0 + lcA * 8;
        const size_t gB = (size_t)lrowB * K + k0 + lcB * 8;
        cp16(s0 + dA,             pAH + gA);
        cp16(s0 + dB,             pAH + gB);
        if (NTERMS == 3) {
            cp16(s0 + PLANE + dA, pAL + gA);
            cp16(s0 + PLANE + dB, pAL + gB);
        }
        cp16(s0 + 2 * PLANE + dA, pBH + gA);
        cp16(s0 + 2 * PLANE + dB, pBH + gB);
        cp16(s0 + 3 * PLANE + dA, pBL + gA);
        cp16(s0 + 3 * PLANE + dB, pBL + gB);
    };

    float acc[4][4][4];
#pragma unroll
    for (int i = 0; i < 4; ++i)
#pragma unroll
        for (int j = 0; j < 4; ++j)
#pragma unroll
            for (int q = 0; q < 4; ++q) acc[i][j][q] = 0.f;

    const int quad = lane >> 3;
    const int l8   = lane & 7;
    const int roff = (quad & 1) * 8 + l8;
    const int kq   = quad >> 1;
    const int xk   = (roff >> 1) & 3;
    const uint32_t swz0 = (uint32_t)(((0 + kq) ^ xk) << 4);
    const uint32_t swz1 = (uint32_t)(((2 + kq) ^ xk) << 4);

    const int nch = K / 32;

    load_stage(0 * STAGEB, 0);  cp_commit();
    load_stage(1 * STAGEB, 32); cp_commit();

    for (int ch = 0; ch < nch; ch += 3) {
#pragma unroll
        for (int u = 0; u < 3; ++u) {
            const int cc = ch + u;
            if (cc >= nch) break;

            cp_wait<1>();
            __syncthreads();

            if (cc + 2 < nch)
                load_stage((uint32_t)(((u + 2) % 3) * STAGEB), (cc + 2) * 32);
            cp_commit();

            const uint32_t sb = sbase + (uint32_t)(u * STAGEB);
#pragma unroll
            for (int s = 0; s < 2; ++s) {
                const uint32_t swz = s ? swz1 : swz0;
                unsigned aH[4][4], aL[4][4];
#pragma unroll
                for (int mt = 0; mt < 4; ++mt) {
                    const uint32_t ra = sb + (wm + mt * 16 + roff) * ROWB + swz;
                    ldsm4(aH[mt], ra);
                    if (NTERMS == 3) ldsm4(aL[mt], ra + PLANE);
                }
                unsigned bfH[2][4], bfL[2][4];
#pragma unroll
                for (int pt = 0; pt < 2; ++pt) {
                    const uint32_t rb = sb + 2 * PLANE
                                      + (wn + pt * 16 + roff) * ROWB + swz;
                    ldsm4(bfH[pt], rb);
                    ldsm4(bfL[pt], rb + PLANE);
                }
#pragma unroll
                for (int mt = 0; mt < 4; ++mt)
#pragma unroll
                    for (int nt = 0; nt < 4; ++nt) {
                        const int pt = nt >> 1, hi = nt & 1;
                        mma_f16_f32(acc[mt][nt][0], acc[mt][nt][1],
                                    acc[mt][nt][2], acc[mt][nt][3],
                                    aH[mt][0], aH[mt][1], aH[mt][2], aH[mt][3],
                                    bfH[pt][hi], bfH[pt][2 + hi]);
                    }
#pragma unroll
                for (int mt = 0; mt < 4; ++mt)
#pragma unroll
                    for (int nt = 0; nt < 4; ++nt) {
                        const int pt = nt >> 1, hi = nt & 1;
                        mma_f16_f32(acc[mt][nt][0], acc[mt][nt][1],
                                    acc[mt][nt][2], acc[mt][nt][3],
                                    aH[mt][0], aH[mt][1], aH[mt][2], aH[mt][3],
                                    bfL[pt][hi], bfL[pt][2 + hi]);
                    }
                if (NTERMS == 3) {
#pragma unroll
                    for (int mt = 0; mt < 4; ++mt)
#pragma unroll
                        for (int nt = 0; nt < 4; ++nt) {
                            const int pt = nt >> 1, hi = nt & 1;
                            mma_f16_f32(acc[mt][nt][0], acc[mt][nt][1],
                                        acc[mt][nt][2], acc[mt][nt][3],
                                        aL[mt][0], aL[mt][1], aL[mt][2], aL[mt][3],
                                        bfH[pt][hi], bfH[pt][2 + hi]);
                        }
                }
            }
        }
    }

    const int r = lane >> 2, c = lane & 3;
#pragma unroll
    for (int mt = 0; mt < 4; ++mt) {
#pragma unroll
        for (int nt = 0; nt < 4; ++nt) {
            const int m = m0 + wm + mt * 16 + r;
            const int n = n0 + wn + nt * 8 + c * 2;
            float2 v0 = make_float2(acc[mt][nt][0], acc[mt][nt][1]);
            float2 v1 = make_float2(acc[mt][nt][2], acc[mt][nt][3]);
            if (MODE == 2) {
                const size_t w0 = ((size_t)z * cBatch + (size_t)m * N + n) >> 1;
                const size_t w1 = ((size_t)z * cBatch + (size_t)(m + 8) * N + n) >> 1;
                unsigned hw, lw;
                split2pack_h(v0.x, v0.y, hw, lw);
                ((unsigned*)CH)[w0] = hw; ((unsigned*)CL)[w0] = lw;
                split2pack_h(v1.x, v1.y, hw, lw);
                ((unsigned*)CH)[w1] = hw; ((unsigned*)CL)[w1] = lw;
            } else {
                const float b0v = bias[n], b1v = bias[n + 1];
                v0.x += b0v; v0.y += b1v;
                v1.x += b0v; v1.y += b1v;
                float* Cz = C + (size_t)z * cBatch;
                *(float2*)(Cz + (size_t)m * N + n)       = v0;
                *(float2*)(Cz + (size_t)(m + 8) * N + n) = v1;
            }
        }
    }
}

// ---------------------------------------------------------------------------
// Gram GEMM: G_b = xt_b xt_b^T (NT, A=B=xt). Upper-tri tiles + mirror write.
// ---------------------------------------------------------------------------
__global__ __launch_bounds__(256)
void gram_gemm()
{
    extern __shared__ char sm[];
    const uint32_t sbase = smem_u32(sm);

    int rem = blockIdx.x, by = 0, len = 8;
    while (rem >= len) { rem -= len; ++by; --len; }
    const int bx = by + rem;
    const int b = blockIdx.z;
    const int m0 = by * 128, n0 = bx * 128;
    const int K = kN;

    const __half* AHp = g_xtH + (size_t)b * kC * kN;
    const __half* ALp = g_xtL + (size_t)b * kC * kN;

    const int t = threadIdx.x;
    const int warp = t >> 5, lane = t & 31;
    const int wm = (warp & 1) * 64;
    const int wn = (warp >> 1) * 32;

    const int lrowA = t >> 2, lcA = t & 3;
    const int lrowB = (t + 256) >> 2, lcB = (t + 256) & 3;
    const uint32_t dA = lrowA * ROWB + ((lcA ^ ((lrowA >> 1) & 3)) << 4);
    const uint32_t dB = lrowB * ROWB + ((lcB ^ ((lrowB >> 1) & 3)) << 4);

    const __half* pAH = AHp + (size_t)m0 * K;
    const __half* pAL = ALp + (size_t)m0 * K;
    const __half* pBH = AHp + (size_t)n0 * K;
    const __half* pBL = ALp + (size_t)n0 * K;

    auto load_stage = [&](uint32_t stoff, int k0) {
        const uint32_t s0 = sbase + stoff;
        const size_t gA = (size_t)lrowA * K + k0 + lcA * 8;
        const size_t gB = (size_t)lrowB * K + k0 + lcB * 8;
        cp16(s0 + dA,             pAH + gA);
        cp16(s0 + dB,             pAH + gB);
        cp16(s0 + PLANE + dA,     pAL + gA);
        cp16(s0 + PLANE + dB,     pAL + gB);
        cp16(s0 + 2 * PLANE + dA, pBH + gA);
        cp16(s0 + 2 * PLANE + dB, pBH + gB);
        cp16(s0 + 3 * PLANE + dA, pBL + gA);
        cp16(s0 + 3 * PLANE + dB, pBL + gB);
    };

    float acc[4][4][4];
#pragma unroll
    for (int i = 0; i < 4; ++i)
#pragma unroll
        for (int j = 0; j < 4; ++j)
#pragma unroll
            for (int q = 0; q < 4; ++q) acc[i][j][q] = 0.f;

    const int quad = lane >> 3;
    const int l8   = lane & 7;
    const int roff = (quad & 1) * 8 + l8;
    const int kq   = quad >> 1;
    const int xk   = (roff >> 1) & 3;
    const uint32_t swz0 = (uint32_t)(((0 + kq) ^ xk) << 4);
    const uint32_t swz1 = (uint32_t)(((2 + kq) ^ xk) << 4);

    const int nch = K / 32;
    load_stage(0 * STAGEB, 0);  cp_commit();
    load_stage(1 * STAGEB, 32); cp_commit();

    for (int ch = 0; ch < nch; ch += 3) {
#pragma unroll
        for (int u = 0; u < 3; ++u) {
            const int cc = ch + u;
            if (cc >= nch) break;
            cp_wait<1>();
            __syncthreads();
            if (cc + 2 < nch)
                load_stage((uint32_t)(((u + 2) % 3) * STAGEB), (cc + 2) * 32);
            cp_commit();

            const uint32_t sb = sbase + (uint32_t)(u * STAGEB);
#pragma unroll
            for (int s = 0; s < 2; ++s) {
                const uint32_t swz = s ? swz1 : swz0;
                unsigned aH[4][4], aL[4][4];
#pragma unroll
                for (int mt = 0; mt < 4; ++mt) {
                    const uint32_t ra = sb + (wm + mt * 16 + roff) * ROWB + swz;
                    ldsm4(aH[mt], ra);
                    ldsm4(aL[mt], ra + PLANE);
                }
                unsigned bfH[2][4], bfL[2][4];
#pragma unroll
                for (int pt = 0; pt < 2; ++pt) {
                    const uint32_t rb = sb + 2 * PLANE
                                      + (wn + pt * 16 + roff) * ROWB + swz;
                    ldsm4(bfH[pt], rb);
                    ldsm4(bfL[pt], rb + PLANE);
                }
#pragma unroll
                for (int mt = 0; mt < 4; ++mt)
#pragma unroll
                    for (int nt = 0; nt < 4; ++nt) {
                        const int pt = nt >> 1, hi = nt & 1;
                        mma_f16_f32(acc[mt][nt][0], acc[mt][nt][1],
                                    acc[mt][nt][2], acc[mt][nt][3],
                                    aH[mt][0], aH[mt][1], aH[mt][2], aH[mt][3],
                                    bfH[pt][hi], bfH[pt][2 + hi]);
                    }
#pragma unroll
                for (int mt = 0; mt < 4; ++mt)
#pragma unroll
                    for (int nt = 0; nt < 4; ++nt) {
                        const int pt = nt >> 1, hi = nt & 1;
                        mma_f16_f32(acc[mt][nt][0], acc[mt][nt][1],
                                    acc[mt][nt][2], acc[mt][nt][3],
                                    aH[mt][0], aH[mt][1], aH[mt][2], aH[mt][3],
                                    bfL[pt][hi], bfL[pt][2 + hi]);
                    }
#pragma unroll
                for (int mt = 0; mt < 4; ++mt)
#pragma unroll
                    for (int nt = 0; nt < 4; ++nt) {
                        const int pt = nt >> 1, hi = nt & 1;
                        mma_f16_f32(acc[mt][nt][0], acc[mt][nt][1],
                                    acc[mt][nt][2], acc[mt][nt][3],
                                    aL[mt][0], aL[mt][1], aL[mt][2], aL[mt][3],
                                    bfH[pt][hi], bfH[pt][2 + hi]);
                    }
            }
        }
    }

    const int r = lane >> 2, c = lane & 3;
    __half* GH = g_GH + (size_t)b * kC * kC;
    __half* GL = g_GL + (size_t)b * kC * kC;
#pragma unroll
    for (int mt = 0; mt < 4; ++mt) {
#pragma unroll
        for (int nt = 0; nt < 4; ++nt) {
            const int m = m0 + wm + mt * 16 + r;
            const int n = n0 + wn + nt * 8 + c * 2;
#pragma unroll
            for (int rr = 0; rr < 2; ++rr) {
                const int mm = m + rr * 8;
                const float va = acc[mt][nt][rr * 2];
                const float vb = acc[mt][nt][rr * 2 + 1];
                unsigned hw, lw;
                split2pack_h(va, vb, hw, lw);
                const size_t w = ((size_t)mm * kC + n) >> 1;
                ((unsigned*)GH)[w] = hw; ((unsigned*)GL)[w] = lw;
                __half ha = __float2half_rn(va);
                __half hb = __float2half_rn(vb);
                GH[(size_t)n * kC + mm] = ha;
                GL[(size_t)n * kC + mm] = __float2half_rn(va - __half2float(ha));
                GH[(size_t)(n + 1) * kC + mm] = hb;
                GL[(size_t)(n + 1) * kC + mm] = __float2half_rn(vb - __half2float(hb));
            }
        }
    }
}

// ---------------------------------------------------------------------------
// logits = T Wq^T per (b,h) + fused softmax -> g_attnP. (R15 winner)
// ---------------------------------------------------------------------------
__global__ __launch_bounds__(256)
void logits_softmax(const float* __restrict__ alpha)
{
    __shared__ unsigned sA[4][32][72];

    const int t = threadIdx.x;
    const int warp = t >> 5, lane = t & 31;
    const int wm = (warp & 1) * 32;
    const int wn = (warp >> 1) * 16;
    const int r = lane >> 2, c = lane & 3;
    const int bh = blockIdx.x;
    const int b = bh >> 4, h = bh & 15;

    const unsigned* srcs[4] = {
        (const unsigned*)g_TH + ((size_t)b * kC + h * 64) * (kC / 2),
        (const unsigned*)g_TL + ((size_t)b * kC + h * 64) * (kC / 2),
        (const unsigned*)g_wqkvH + (size_t)(h * 64) * (kC / 2),
        (const unsigned*)g_wqkvL + (size_t)(h * 64) * (kC / 2) };

    float acc[2][2][4];
#pragma unroll
    for (int i = 0; i < 2; ++i)
#pragma unroll
        for (int j = 0; j < 2; ++j)
#pragma unroll
            for (int q = 0; q < 4; ++q) acc[i][j][q] = 0.f;

    for (int kc = 0; kc < 16; ++kc) {
#pragma unroll
        for (int i = 0; i < 8; ++i) {
            const int idx = t + 256 * i;
            const int arr = idx >> 9;
            const int rem = idx & 511;
            const int row = rem >> 3;
            const int q4  = rem & 7;
            uint4 v = ((const uint4*)(srcs[arr] + (size_t)row * (kC / 2)
                                      + kc * 32))[q4];
            sA[arr][q4 * 4 + 0][row] = v.x;
            sA[arr][q4 * 4 + 1][row] = v.y;
            sA[arr][q4 * 4 + 2][row] = v.z;
            sA[arr][q4 * 4 + 3][row] = v.w;
        }
        __syncthreads();

#pragma unroll
        for (int s = 0; s < 4; ++s) {
            const int base = 8 * s;
            unsigned aH[2][4], aL[2][4], bH[2][2], bL[2][2];
#pragma unroll
            for (int mt = 0; mt < 2; ++mt) {
                const int mr = wm + mt * 16 + r;
                aH[mt][0] = sA[0][base + c][mr];     aH[mt][1] = sA[0][base + c][mr + 8];
                aH[mt][2] = sA[0][base + c + 4][mr]; aH[mt][3] = sA[0][base + c + 4][mr + 8];
                aL[mt][0] = sA[1][base + c][mr];     aL[mt][1] = sA[1][base + c][mr + 8];
                aL[mt][2] = sA[1][base + c + 4][mr]; aL[mt][3] = sA[1][base + c + 4][mr + 8];
            }
#pragma unroll
            for (int nt = 0; nt < 2; ++nt) {
                const int nr = wn + nt * 8 + r;
                bH[nt][0] = sA[2][base + c][nr]; bH[nt][1] = sA[2][base + c + 4][nr];
                bL[nt][0] = sA[3][base + c][nr]; bL[nt][1] = sA[3][base + c + 4][nr];
            }
#pragma unroll
            for (int mt = 0; mt < 2; ++mt)
#pragma unroll
                for (int nt = 0; nt < 2; ++nt) {
                    mma_f16_f32(acc[mt][nt][0], acc[mt][nt][1], acc[mt][nt][2], acc[mt][nt][3],
                                aH[mt][0], aH[mt][1], aH[mt][2], aH[mt][3],
                                bL[nt][0], bL[nt][1]);
                    mma_f16_f32(acc[mt][nt][0], acc[mt][nt][1], acc[mt][nt][2], acc[mt][nt][3],
                                aL[mt][0], aL[mt][1], aL[mt][2], aL[mt][3],
                                bH[nt][0], bH[nt][1]);
                    mma_f16_f32(acc[mt][nt][0], acc[mt][nt][1], acc[mt][nt][2], acc[mt][nt][3],
                                aH[mt][0], aH[mt][1], aH[mt][2], aH[mt][3],
                                bH[nt][0], bH[nt][1]);
                }
        }
        __syncthreads();
    }

    float* L = (float*)&sA[0][0][0];     // 64 x 65
#pragma unroll
    for (int mt = 0; mt < 2; ++mt)
#pragma unroll
        for (int nt = 0; nt < 2; ++nt) {
            const int dr = wm + mt * 16 + r;
            const int e0 = wn + nt * 8 + 2 * c;
            L[dr * 65 + e0]           = acc[mt][nt][0];
            L[dr * 65 + e0 + 1]       = acc[mt][nt][1];
            L[(dr + 8) * 65 + e0]     = acc[mt][nt][2];
            L[(dr + 8) * 65 + e0 + 1] = acc[mt][nt][3];
        }
    __syncthreads();

    if (t < 64) {
        const float inva = 1.0f / alpha[h];
        float mx = -1e30f;
        for (int e = 0; e < 64; ++e)
            mx = fmaxf(mx, L[t * 65 + e] * inva);
        float sum = 0.f;
        float* P = g_attnP + (size_t)bh * (kD * kD) + t * kD;
        for (int e = 0; e < 64; ++e) {
            const float ex = expf(L[t * 65 + e] * inva - mx);
            L[t * 65 + e] = ex;
            sum += ex;
        }
        const float inv = 1.0f / sum;
        for (int e = 0; e < 64; ++e)
            P[e] = L[t * 65 + e] * inv;
    }
}

// ---------------------------------------------------------------------------
// U kernel: Ut_b[c, h*64+d] = sum_e Wv[h*64+e, c] * P_bh[d, e]   (fp32 FMA)
// grid (kH, kB), 256 thr. c tiled by 64; per tile each thread: 16 d-outputs.
// ---------------------------------------------------------------------------
__global__ __launch_bounds__(256)
void u_kernel()
{
    __shared__ float Ps[64][65];
    __shared__ float Wv[64][65];     // [e][c_local]

    const int h = blockIdx.x, b = blockIdx.y;
    const int t = threadIdx.x;

    const float* P = g_attnP + ((size_t)b * kH + h) * (kD * kD);
#pragma unroll
    for (int i = 0; i < 16; ++i) {
        const int idx = t + 256 * i;
        Ps[idx >> 6][idx & 63] = P[idx];
    }

    const __half* WvH = g_wqkvH + (size_t)(2048 + h * 64) * kC;
    const __half* WvL = g_wqkvL + (size_t)(2048 + h * 64) * kC;

    const int cl = t & 63;
    const int dg = (t >> 6) * 16;    // d base: 0,16,32,48

    for (int ct = 0; ct < 16; ++ct) {
        __syncthreads();
        // load Wv tile [64 e][64 c] as fp32 = hi + lo
#pragma unroll
        for (int i = 0; i < 16; ++i) {
            const int idx = t + 256 * i;
            const int e = idx >> 6, c = idx & 63;
            const size_t o = (size_t)e * kC + ct * 64 + c;
            Wv[e][c] = __half2float(WvH[o]) + __half2float(WvL[o]);
        }
        __syncthreads();

        __half outv[32];
#pragma unroll
        for (int dd = 0; dd < 16; ++dd) {
            const int d = dg + dd;
            float acc = 0.f;
#pragma unroll
            for (int e = 0; e < 64; ++e)
                acc = fmaf(Ps[d][e], Wv[e][cl], acc);
            __half hv = __float2half_rn(acc);
            outv[dd] = hv;
            outv[16 + dd] = __float2half_rn(acc - __half2float(hv));
        }
        const size_t o = ((size_t)b * kC + ct * 64 + cl) * kC + h * 64 + dg;
#pragma unroll
        for (int dd = 0; dd < 16; ++dd) {
            g_UtH[o + dd] = outv[dd];
            g_UtL[o + dd] = outv[16 + dd];
        }
    }
}

// ---------------------------------------------------------------------------
extern "C" void kernel_launch(void* const* d_in, const int* in_sizes, int n_in,
                              void* d_out, int out_size)
{
    const float* x = nullptr;
    const float* Wqkv = nullptr;
    const float* Wproj = nullptr;
    const float* bproj = nullptr;
    const float* alpha = nullptr;
    for (int i = 0; i < n_in; ++i) {
        switch (in_sizes[i]) {
            case kM * kC:    x     = (const float*)d_in[i]; break;
            case kQKV * kC:  Wqkv  = (const float*)d_in[i]; break;
            case kC * kC:    Wproj = (const float*)d_in[i]; break;
            case kC:         bproj = (const float*)d_in[i]; break;
            case kH:         alpha = (const float*)d_in[i]; break;
            default: break;
        }
    }

    __half *xH, *xL, *wqH, *wqL, *wpH, *wpL, *gH, *gL, *tH, *tL;
    __half *utH, *utL, *w2H, *w2L;
    cudaGetSymbolAddress((void**)&xH, g_xH);     cudaGetSymbolAddress((void**)&xL, g_xL);
    cudaGetSymbolAddress((void**)&wqH, g_wqkvH); cudaGetSymbolAddress((void**)&wqL, g_wqkvL);
    cudaGetSymbolAddress((void**)&wpH, g_wprojH); cudaGetSymbolAddress((void**)&wpL, g_wprojL);
    cudaGetSymbolAddress((void**)&gH, g_GH);     cudaGetSymbolAddress((void**)&gL, g_GL);
    cudaGetSymbolAddress((void**)&tH, g_TH);     cudaGetSymbolAddress((void**)&tL, g_TL);
    cudaGetSymbolAddress((void**)&utH, g_UtH);   cudaGetSymbolAddress((void**)&utL, g_UtL);
    cudaGetSymbolAddress((void**)&w2H, g_W2H);   cudaGetSymbolAddress((void**)&w2L, g_W2L);

    cudaFuncSetAttribute(f16_gemm<0, 2>, cudaFuncAttributeMaxDynamicSharedMemorySize, SMEM_GEMM);
    cudaFuncSetAttribute(f16_gemm<2, 3>, cudaFuncAttributeMaxDynamicSharedMemorySize, SMEM_GEMM);
    cudaFuncSetAttribute(gram_gemm,      cudaFuncAttributeMaxDynamicSharedMemorySize, SMEM_GEMM);

    // 0) splits + transpose-split
    {
        int n4 = kM * kC / 4;
        split_kernel<<<(n4 + 255) / 256, 256>>>(x, xH, xL, n4);
        n4 = kQKV * kC / 4;
        split_kernel<<<(n4 + 255) / 256, 256>>>(Wqkv, wqH, wqL, n4);
        n4 = kC * kC / 4;
        split_kernel<<<(n4 + 255) / 256, 256>>>(Wproj, wpH, wpL, n4);
        transpose_split_kernel<<<dim3(kC / 32, kM / 32), 256>>>(x);
    }

    // 1) Gram: G_b = x_b^T x_b (upper-tri + mirror, 3-term)
    gram_gemm<<<dim3(36, 1, kB), 256, SMEM_GEMM>>>();

    // 2) T_b = Wk G_b (3-term, split out)
    f16_gemm<2, 3><<<dim3(kC / 128, kC / 128, kB), 256, SMEM_GEMM>>>(
        wqH + (size_t)1024 * kC, wqL + (size_t)1024 * kC, gH, gL,
        nullptr, nullptr, tH, tL, kC, kC, kC,
        0, (size_t)kC * kC, (size_t)kC * kC);

    // 3) logits = T Wq^T per head + fused softmax -> g_attnP
    logits_softmax<<<kB * kH, 256>>>(alpha);

    // 4) Ut_b[c, hd] = sum_e Wv[he,c] P_bh[d,e]  (fp32 FMA, split out)
    u_kernel<<<dim3(kH, kB), 256>>>();

    // 5) W''_b[o,c] = sum_hd Wproj[o,hd] Ut_b[c,hd]  (3-term, split out)
    f16_gemm<2, 3><<<dim3(kC / 128, kC / 128, kB), 256, SMEM_GEMM>>>(
        wpH, wpL, utH, utL,
        nullptr, nullptr, w2H, w2L, kC, kC, kC,
        0, (size_t)kC * kC, (size_t)kC * kC);

    // 6) y_b = x_b W''_b^T + bias  (2-term)
    f16_gemm<0, 2><<<dim3(kC / 128, kN / 128, kB), 256, SMEM_GEMM>>>(
        xH, xL, w2H, w2L,
        (float*)d_out, bproj, nullptr, nullptr, kN, kC, kC,
        (size_t)kN * kC, (size_t)kC * kC, (size_t)kN * kC);
}

// round 17
// speedup vs baseline: 1.2632x; 1.2632x over previous
#include <cuda_runtime.h>
#include <cuda_fp16.h>
#include <cstdint>

// ---------------------------------------------------------------------------
// SpectralMSA channel attention — Round 17: R16 folded pipeline with U on
// tensor cores (pv_mma-style 64x64x64 mma per (ctile, b, h)).
//   logits: G = x^T x (sym tri+mirror), T = Wk G, logits = T Wq^T + softmax.
//   output: Ut_b[c,hd] = sum_e Wv[he,c] P_bh[d,e]   (mma, 3-term)
//           W''_b = Wproj Ut_b^T-contraction        (mma, 3-term)
//           y_b   = x_b W''_b^T + bias              (mma, 2-term)
// ---------------------------------------------------------------------------

namespace {
constexpr int kB = 4;
constexpr int kN = 4096;
constexpr int kC = 1024;
constexpr int kH = 16;
constexpr int kD = 64;
constexpr int kM = kB * kN;        // 16384
constexpr int kQKV = 3 * kC;       // 3072
}

// fp32 scratch
__device__ float g_attnP[(size_t)kB * kH * kD * kD];
// split-fp16 operands
__device__ __half g_xH[(size_t)kM * kC],       g_xL[(size_t)kM * kC];
__device__ __half g_xtH[(size_t)kB * kC * kN], g_xtL[(size_t)kB * kC * kN];
__device__ __half g_wqkvH[(size_t)kQKV * kC],  g_wqkvL[(size_t)kQKV * kC];
__device__ __half g_wprojH[(size_t)kC * kC],   g_wprojL[(size_t)kC * kC];
__device__ __half g_GH[(size_t)kB * kC * kC],  g_GL[(size_t)kB * kC * kC];
__device__ __half g_TH[(size_t)kB * kC * kC],  g_TL[(size_t)kB * kC * kC];
__device__ __half g_UtH[(size_t)kB * kC * kC], g_UtL[(size_t)kB * kC * kC];  // [b][c][hd]
__device__ __half g_W2H[(size_t)kB * kC * kC], g_W2L[(size_t)kB * kC * kC];  // [b][o][c]

// ---------------- low-level helpers ----------------------------------------
__device__ __forceinline__ void mma_f16_f32(float& d0, float& d1, float& d2, float& d3,
                                            unsigned a0, unsigned a1, unsigned a2, unsigned a3,
                                            unsigned b0, unsigned b1)
{
    asm volatile(
        "mma.sync.aligned.m16n8k16.row.col.f32.f16.f16.f32 "
        "{%0,%1,%2,%3},{%4,%5,%6,%7},{%8,%9},{%0,%1,%2,%3};"
        : "+f"(d0), "+f"(d1), "+f"(d2), "+f"(d3)
        : "r"(a0), "r"(a1), "r"(a2), "r"(a3), "r"(b0), "r"(b1));
}
__device__ __forceinline__ void split2pack_h(float a, float b, unsigned& h, unsigned& l)
{
    __half ha = __float2half_rn(a), hb = __float2half_rn(b);
    __half2 ph(ha, hb); h = *(unsigned*)&ph;
    __half2 pl(__float2half_rn(a - __half2float(ha)),
               __float2half_rn(b - __half2float(hb)));
    l = *(unsigned*)&pl;
}
__device__ __forceinline__ uint32_t smem_u32(const void* p) {
    uint32_t a;
    asm("{ .reg .u64 t; cvta.to.shared.u64 t, %1; cvt.u32.u64 %0, t; }"
        : "=r"(a) : "l"(p));
    return a;
}
__device__ __forceinline__ void cp16(uint32_t dst, const void* src) {
    asm volatile("cp.async.cg.shared.global [%0], [%1], 16;" :: "r"(dst), "l"(src));
}
__device__ __forceinline__ void cp_commit() {
    asm volatile("cp.async.commit_group;" ::: "memory");
}
template <int N>
__device__ __forceinline__ void cp_wait() {
    asm volatile("cp.async.wait_group %0;" :: "n"(N) : "memory");
}
__device__ __forceinline__ void ldsm4(unsigned* r, uint32_t addr) {
    asm volatile("ldmatrix.sync.aligned.m8n8.x4.shared.b16 {%0,%1,%2,%3}, [%4];"
                 : "=r"(r[0]), "=r"(r[1]), "=r"(r[2]), "=r"(r[3]) : "r"(addr));
}

// ---------------------------------------------------------------------------
__global__ void split_kernel(const float* __restrict__ src,
                             __half* __restrict__ hi,
                             __half* __restrict__ lo, int n4)
{
    int i = blockIdx.x * blockDim.x + threadIdx.x;
    if (i >= n4) return;
    float4 v = ((const float4*)src)[i];
    unsigned h0, h1, l0, l1;
    split2pack_h(v.x, v.y, h0, l0);
    split2pack_h(v.z, v.w, h1, l1);
    ((uint2*)hi)[i] = make_uint2(h0, h1);
    ((uint2*)lo)[i] = make_uint2(l0, l1);
}

// transpose + split: x [B*N, C] fp32 -> xt [B][C][N] fp16 hi/lo
__global__ __launch_bounds__(256)
void transpose_split_kernel(const float* __restrict__ x)
{
    __shared__ float s[32][33];
    const int c0 = blockIdx.x * 32;
    const int n0 = blockIdx.y * 32;
    const int t = threadIdx.x;
    const int tc = t & 31, tr = t >> 5;

#pragma unroll
    for (int i = 0; i < 4; ++i) {
        const int row = tr + i * 8;
        s[row][tc] = x[(size_t)(n0 + row) * kC + c0 + tc];
    }
    __syncthreads();

    const int b = n0 >> 12;
    const int nb = n0 & 4095;
#pragma unroll
    for (int i = 0; i < 4; ++i) {
        const int cc = tr + i * 8;
        const float v = s[tc][cc];
        __half hv = __float2half_rn(v);
        const size_t o = ((size_t)b * kC + c0 + cc) * kN + nb + tc;
        g_xtH[o] = hv;
        g_xtL[o] = __float2half_rn(v - __half2float(hv));
    }
}

// ---------------------------------------------------------------------------
// Unified fp16-split GEMM (NT): 3-stage k32 cp.async ring, XOR swizzle.
// MODE 0: fp32 C + bias (+ per-z batch offset). MODE 2: split fp16 out.
// NTERMS = 2 (HH+HL) or 3 (+LH).
// ---------------------------------------------------------------------------
namespace {
constexpr int ROWB   = 64;
constexpr int PLANE  = 128 * ROWB;       // 8192 B
constexpr int STAGEB = 4 * PLANE;        // 32768 B
constexpr int SMEM_GEMM = 3 * STAGEB;    // 98304 B
}

template <int MODE, int NTERMS>
__global__ __launch_bounds__(256)
void f16_gemm(const __half* __restrict__ AH, const __half* __restrict__ AL,
              const __half* __restrict__ BH, const __half* __restrict__ BL,
              float* __restrict__ C, const float* __restrict__ bias,
              __half* __restrict__ CH, __half* __restrict__ CL,
              int M, int N, int K,
              size_t aBatch, size_t bBatch, size_t cBatch)
{
    extern __shared__ char sm[];
    const uint32_t sbase = smem_u32(sm);

    const int z = blockIdx.z;
    AH += (size_t)z * aBatch; AL += (size_t)z * aBatch;
    BH += (size_t)z * bBatch; BL += (size_t)z * bBatch;

    const int t = threadIdx.x;
    const int warp = t >> 5, lane = t & 31;
    const int wm = (warp & 1) * 64;
    const int wn = (warp >> 1) * 32;
    const int m0 = blockIdx.y * 128, n0 = blockIdx.x * 128;

    const int lrowA = t >> 2, lcA = t & 3;
    const int lrowB = (t + 256) >> 2, lcB = (t + 256) & 3;
    const uint32_t dA = lrowA * ROWB + ((lcA ^ ((lrowA >> 1) & 3)) << 4);
    const uint32_t dB = lrowB * ROWB + ((lcB ^ ((lrowB >> 1) & 3)) << 4);

    const __half* pAH = AH + (size_t)m0 * K;
    const __half* pAL = AL + (size_t)m0 * K;
    const __half* pBH = BH + (size_t)n0 * K;
    const __half* pBL = BL + (size_t)n0 * K;

    auto load_stage = [&](uint32_t stoff, int k0) {
        const uint32_t s0 = sbase + stoff;
        const size_t gA = (size_t)lrowA * K + k0 + lcA * 8;
        const size_t gB = (size_t)lrowB * K + k0 + lcB * 8;
        cp16(s0 + dA,             pAH + gA);
        cp16(s0 + dB,             pAH + gB);
        if (NTERMS == 3) {
            cp16(s0 + PLANE + dA, pAL + gA);
            cp16(s0 + PLANE + dB, pAL + gB);
        }
        cp16(s0 + 2 * PLANE + dA, pBH + gA);
        cp16(s0 + 2 * PLANE + dB, pBH + gB);
        cp16(s0 + 3 * PLANE + dA, pBL + gA);
        cp16(s0 + 3 * PLANE + dB, pBL + gB);
    };

    float acc[4][4][4];
#pragma unroll
    for (int i = 0; i < 4; ++i)
#pragma unroll
        for (int j = 0; j < 4; ++j)
#pragma unroll
            for (int q = 0; q < 4; ++q) acc[i][j][q] = 0.f;

    const int quad = lane >> 3;
    const int l8   = lane & 7;
    const int roff = (quad & 1) * 8 + l8;
    const int kq   = quad >> 1;
    const int xk   = (roff >> 1) & 3;
    const uint32_t swz0 = (uint32_t)(((0 + kq) ^ xk) << 4);
    const uint32_t swz1 = (uint32_t)(((2 + kq) ^ xk) << 4);

    const int nch = K / 32;

    load_stage(0 * STAGEB, 0);  cp_commit();
    load_stage(1 * STAGEB, 32); cp_commit();

    for (int ch = 0; ch < nch; ch += 3) {
#pragma unroll
        for (int u = 0; u < 3; ++u) {
            const int cc = ch + u;
            if (cc >= nch) break;

            cp_wait<1>();
            __syncthreads();

            if (cc + 2 < nch)
                load_stage((uint32_t)(((u + 2) % 3) * STAGEB), (cc + 2) * 32);
            cp_commit();

            const uint32_t sb = sbase + (uint32_t)(u * STAGEB);
#pragma unroll
            for (int s = 0; s < 2; ++s) {
                const uint32_t swz = s ? swz1 : swz0;
                unsigned aH[4][4], aL[4][4];
#pragma unroll
                for (int mt = 0; mt < 4; ++mt) {
                    const uint32_t ra = sb + (wm + mt * 16 + roff) * ROWB + swz;
                    ldsm4(aH[mt], ra);
                    if (NTERMS == 3) ldsm4(aL[mt], ra + PLANE);
                }
                unsigned bfH[2][4], bfL[2][4];
#pragma unroll
                for (int pt = 0; pt < 2; ++pt) {
                    const uint32_t rb = sb + 2 * PLANE
                                      + (wn + pt * 16 + roff) * ROWB + swz;
                    ldsm4(bfH[pt], rb);
                    ldsm4(bfL[pt], rb + PLANE);
                }
#pragma unroll
                for (int mt = 0; mt < 4; ++mt)
#pragma unroll
                    for (int nt = 0; nt < 4; ++nt) {
                        const int pt = nt >> 1, hi = nt & 1;
                        mma_f16_f32(acc[mt][nt][0], acc[mt][nt][1],
                                    acc[mt][nt][2], acc[mt][nt][3],
                                    aH[mt][0], aH[mt][1], aH[mt][2], aH[mt][3],
                                    bfH[pt][hi], bfH[pt][2 + hi]);
                    }
#pragma unroll
                for (int mt = 0; mt < 4; ++mt)
#pragma unroll
                    for (int nt = 0; nt < 4; ++nt) {
                        const int pt = nt >> 1, hi = nt & 1;
                        mma_f16_f32(acc[mt][nt][0], acc[mt][nt][1],
                                    acc[mt][nt][2], acc[mt][nt][3],
                                    aH[mt][0], aH[mt][1], aH[mt][2], aH[mt][3],
                                    bfL[pt][hi], bfL[pt][2 + hi]);
                    }
                if (NTERMS == 3) {
#pragma unroll
                    for (int mt = 0; mt < 4; ++mt)
#pragma unroll
                        for (int nt = 0; nt < 4; ++nt) {
                            const int pt = nt >> 1, hi = nt & 1;
                            mma_f16_f32(acc[mt][nt][0], acc[mt][nt][1],
                                        acc[mt][nt][2], acc[mt][nt][3],
                                        aL[mt][0], aL[mt][1], aL[mt][2], aL[mt][3],
                                        bfH[pt][hi], bfH[pt][2 + hi]);
                        }
                }
            }
        }
    }

    const int r = lane >> 2, c = lane & 3;
#pragma unroll
    for (int mt = 0; mt < 4; ++mt) {
#pragma unroll
        for (int nt = 0; nt < 4; ++nt) {
            const int m = m0 + wm + mt * 16 + r;
            const int n = n0 + wn + nt * 8 + c * 2;
            float2 v0 = make_float2(acc[mt][nt][0], acc[mt][nt][1]);
            float2 v1 = make_float2(acc[mt][nt][2], acc[mt][nt][3]);
            if (MODE == 2) {
                const size_t w0 = ((size_t)z * cBatch + (size_t)m * N + n) >> 1;
                const size_t w1 = ((size_t)z * cBatch + (size_t)(m + 8) * N + n) >> 1;
                unsigned hw, lw;
                split2pack_h(v0.x, v0.y, hw, lw);
                ((unsigned*)CH)[w0] = hw; ((unsigned*)CL)[w0] = lw;
                split2pack_h(v1.x, v1.y, hw, lw);
                ((unsigned*)CH)[w1] = hw; ((unsigned*)CL)[w1] = lw;
            } else {
                const float b0v = bias[n], b1v = bias[n + 1];
                v0.x += b0v; v0.y += b1v;
                v1.x += b0v; v1.y += b1v;
                float* Cz = C + (size_t)z * cBatch;
                *(float2*)(Cz + (size_t)m * N + n)       = v0;
                *(float2*)(Cz + (size_t)(m + 8) * N + n) = v1;
            }
        }
    }
}

// ---------------------------------------------------------------------------
// Gram GEMM: G_b = xt_b xt_b^T. Upper-tri tiles + mirror write. (R15 winner)
// ---------------------------------------------------------------------------
__global__ __launch_bounds__(256)
void gram_gemm()
{
    extern __shared__ char sm[];
    const uint32_t sbase = smem_u32(sm);

    int rem = blockIdx.x, by = 0, len = 8;
    while (rem >= len) { rem -= len; ++by; --len; }
    const int bx = by + rem;
    const int b = blockIdx.z;
    const int m0 = by * 128, n0 = bx * 128;
    const int K = kN;

    const __half* AHp = g_xtH + (size_t)b * kC * kN;
    const __half* ALp = g_xtL + (size_t)b * kC * kN;

    const int t = threadIdx.x;
    const int warp = t >> 5, lane = t & 31;
    const int wm = (warp & 1) * 64;
    const int wn = (warp >> 1) * 32;

    const int lrowA = t >> 2, lcA = t & 3;
    const int lrowB = (t + 256) >> 2, lcB = (t + 256) & 3;
    const uint32_t dA = lrowA * ROWB + ((lcA ^ ((lrowA >> 1) & 3)) << 4);
    const uint32_t dB = lrowB * ROWB + ((lcB ^ ((lrowB >> 1) & 3)) << 4);

    const __half* pAH = AHp + (size_t)m0 * K;
    const __half* pAL = ALp + (size_t)m0 * K;
    const __half* pBH = AHp + (size_t)n0 * K;
    const __half* pBL = ALp + (size_t)n0 * K;

    auto load_stage = [&](uint32_t stoff, int k0) {
        const uint32_t s0 = sbase + stoff;
        const size_t gA = (size_t)lrowA * K + k0 + lcA * 8;
        const size_t gB = (size_t)lrowB * K + k0 + lcB * 8;
        cp16(s0 + dA,             pAH + gA);
        cp16(s0 + dB,             pAH + gB);
        cp16(s0 + PLANE + dA,     pAL + gA);
        cp16(s0 + PLANE + dB,     pAL + gB);
        cp16(s0 + 2 * PLANE + dA, pBH + gA);
        cp16(s0 + 2 * PLANE + dB, pBH + gB);
        cp16(s0 + 3 * PLANE + dA, pBL + gA);
        cp16(s0 + 3 * PLANE + dB, pBL + gB);
    };

    float acc[4][4][4];
#pragma unroll
    for (int i = 0; i < 4; ++i)
#pragma unroll
        for (int j = 0; j < 4; ++j)
#pragma unroll
            for (int q = 0; q < 4; ++q) acc[i][j][q] = 0.f;

    const int quad = lane >> 3;
    const int l8   = lane & 7;
    const int roff = (quad & 1) * 8 + l8;
    const int kq   = quad >> 1;
    const int xk   = (roff >> 1) & 3;
    const uint32_t swz0 = (uint32_t)(((0 + kq) ^ xk) << 4);
    const uint32_t swz1 = (uint32_t)(((2 + kq) ^ xk) << 4);

    const int nch = K / 32;
    load_stage(0 * STAGEB, 0);  cp_commit();
    load_stage(1 * STAGEB, 32); cp_commit();

    for (int ch = 0; ch < nch; ch += 3) {
#pragma unroll
        for (int u = 0; u < 3; ++u) {
            const int cc = ch + u;
            if (cc >= nch) break;
            cp_wait<1>();
            __syncthreads();
            if (cc + 2 < nch)
                load_stage((uint32_t)(((u + 2) % 3) * STAGEB), (cc + 2) * 32);
            cp_commit();

            const uint32_t sb = sbase + (uint32_t)(u * STAGEB);
#pragma unroll
            for (int s = 0; s < 2; ++s) {
                const uint32_t swz = s ? swz1 : swz0;
                unsigned aH[4][4], aL[4][4];
#pragma unroll
                for (int mt = 0; mt < 4; ++mt) {
                    const uint32_t ra = sb + (wm + mt * 16 + roff) * ROWB + swz;
                    ldsm4(aH[mt], ra);
                    ldsm4(aL[mt], ra + PLANE);
                }
                unsigned bfH[2][4], bfL[2][4];
#pragma unroll
                for (int pt = 0; pt < 2; ++pt) {
                    const uint32_t rb = sb + 2 * PLANE
                                      + (wn + pt * 16 + roff) * ROWB + swz;
                    ldsm4(bfH[pt], rb);
                    ldsm4(bfL[pt], rb + PLANE);
                }
#pragma unroll
                for (int mt = 0; mt < 4; ++mt)
#pragma unroll
                    for (int nt = 0; nt < 4; ++nt) {
                        const int pt = nt >> 1, hi = nt & 1;
                        mma_f16_f32(acc[mt][nt][0], acc[mt][nt][1],
                                    acc[mt][nt][2], acc[mt][nt][3],
                                    aH[mt][0], aH[mt][1], aH[mt][2], aH[mt][3],
                                    bfH[pt][hi], bfH[pt][2 + hi]);
                    }
#pragma unroll
                for (int mt = 0; mt < 4; ++mt)
#pragma unroll
                    for (int nt = 0; nt < 4; ++nt) {
                        const int pt = nt >> 1, hi = nt & 1;
                        mma_f16_f32(acc[mt][nt][0], acc[mt][nt][1],
                                    acc[mt][nt][2], acc[mt][nt][3],
                                    aH[mt][0], aH[mt][1], aH[mt][2], aH[mt][3],
                                    bfL[pt][hi], bfL[pt][2 + hi]);
                    }
#pragma unroll
                for (int mt = 0; mt < 4; ++mt)
#pragma unroll
                    for (int nt = 0; nt < 4; ++nt) {
                        const int pt = nt >> 1, hi = nt & 1;
                        mma_f16_f32(acc[mt][nt][0], acc[mt][nt][1],
                                    acc[mt][nt][2], acc[mt][nt][3],
                                    aL[mt][0], aL[mt][1], aL[mt][2], aL[mt][3],
                                    bfH[pt][hi], bfH[pt][2 + hi]);
                    }
            }
        }
    }

    const int r = lane >> 2, c = lane & 3;
    __half* GH = g_GH + (size_t)b * kC * kC;
    __half* GL = g_GL + (size_t)b * kC * kC;
#pragma unroll
    for (int mt = 0; mt < 4; ++mt) {
#pragma unroll
        for (int nt = 0; nt < 4; ++nt) {
            const int m = m0 + wm + mt * 16 + r;
            const int n = n0 + wn + nt * 8 + c * 2;
#pragma unroll
            for (int rr = 0; rr < 2; ++rr) {
                const int mm = m + rr * 8;
                const float va = acc[mt][nt][rr * 2];
                const float vb = acc[mt][nt][rr * 2 + 1];
                unsigned hw, lw;
                split2pack_h(va, vb, hw, lw);
                const size_t w = ((size_t)mm * kC + n) >> 1;
                ((unsigned*)GH)[w] = hw; ((unsigned*)GL)[w] = lw;
                __half ha = __float2half_rn(va);
                __half hb = __float2half_rn(vb);
                GH[(size_t)n * kC + mm] = ha;
                GL[(size_t)n * kC + mm] = __float2half_rn(va - __half2float(ha));
                GH[(size_t)(n + 1) * kC + mm] = hb;
                GL[(size_t)(n + 1) * kC + mm] = __float2half_rn(vb - __half2float(hb));
            }
        }
    }
}

// ---------------------------------------------------------------------------
// logits = T Wq^T per (b,h) + fused softmax -> g_attnP. (R15 winner)
// ---------------------------------------------------------------------------
__global__ __launch_bounds__(256)
void logits_softmax(const float* __restrict__ alpha)
{
    __shared__ unsigned sA[4][32][72];

    const int t = threadIdx.x;
    const int warp = t >> 5, lane = t & 31;
    const int wm = (warp & 1) * 32;
    const int wn = (warp >> 1) * 16;
    const int r = lane >> 2, c = lane & 3;
    const int bh = blockIdx.x;
    const int b = bh >> 4, h = bh & 15;

    const unsigned* srcs[4] = {
        (const unsigned*)g_TH + ((size_t)b * kC + h * 64) * (kC / 2),
        (const unsigned*)g_TL + ((size_t)b * kC + h * 64) * (kC / 2),
        (const unsigned*)g_wqkvH + (size_t)(h * 64) * (kC / 2),
        (const unsigned*)g_wqkvL + (size_t)(h * 64) * (kC / 2) };

    float acc[2][2][4];
#pragma unroll
    for (int i = 0; i < 2; ++i)
#pragma unroll
        for (int j = 0; j < 2; ++j)
#pragma unroll
            for (int q = 0; q < 4; ++q) acc[i][j][q] = 0.f;

    for (int kc = 0; kc < 16; ++kc) {
#pragma unroll
        for (int i = 0; i < 8; ++i) {
            const int idx = t + 256 * i;
            const int arr = idx >> 9;
            const int rem = idx & 511;
            const int row = rem >> 3;
            const int q4  = rem & 7;
            uint4 v = ((const uint4*)(srcs[arr] + (size_t)row * (kC / 2)
                                      + kc * 32))[q4];
            sA[arr][q4 * 4 + 0][row] = v.x;
            sA[arr][q4 * 4 + 1][row] = v.y;
            sA[arr][q4 * 4 + 2][row] = v.z;
            sA[arr][q4 * 4 + 3][row] = v.w;
        }
        __syncthreads();

#pragma unroll
        for (int s = 0; s < 4; ++s) {
            const int base = 8 * s;
            unsigned aH[2][4], aL[2][4], bH[2][2], bL[2][2];
#pragma unroll
            for (int mt = 0; mt < 2; ++mt) {
                const int mr = wm + mt * 16 + r;
                aH[mt][0] = sA[0][base + c][mr];     aH[mt][1] = sA[0][base + c][mr + 8];
                aH[mt][2] = sA[0][base + c + 4][mr]; aH[mt][3] = sA[0][base + c + 4][mr + 8];
                aL[mt][0] = sA[1][base + c][mr];     aL[mt][1] = sA[1][base + c][mr + 8];
                aL[mt][2] = sA[1][base + c + 4][mr]; aL[mt][3] = sA[1][base + c + 4][mr + 8];
            }
#pragma unroll
            for (int nt = 0; nt < 2; ++nt) {
                const int nr = wn + nt * 8 + r;
                bH[nt][0] = sA[2][base + c][nr]; bH[nt][1] = sA[2][base + c + 4][nr];
                bL[nt][0] = sA[3][base + c][nr]; bL[nt][1] = sA[3][base + c + 4][nr];
            }
#pragma unroll
            for (int mt = 0; mt < 2; ++mt)
#pragma unroll
                for (int nt = 0; nt < 2; ++nt) {
                    mma_f16_f32(acc[mt][nt][0], acc[mt][nt][1], acc[mt][nt][2], acc[mt][nt][3],
                                aH[mt][0], aH[mt][1], aH[mt][2], aH[mt][3],
                                bL[nt][0], bL[nt][1]);
                    mma_f16_f32(acc[mt][nt][0], acc[mt][nt][1], acc[mt][nt][2], acc[mt][nt][3],
                                aL[mt][0], aL[mt][1], aL[mt][2], aL[mt][3],
                                bH[nt][0], bH[nt][1]);
                    mma_f16_f32(acc[mt][nt][0], acc[mt][nt][1], acc[mt][nt][2], acc[mt][nt][3],
                                aH[mt][0], aH[mt][1], aH[mt][2], aH[mt][3],
                                bH[nt][0], bH[nt][1]);
                }
        }
        __syncthreads();
    }

    float* L = (float*)&sA[0][0][0];     // 64 x 65
#pragma unroll
    for (int mt = 0; mt < 2; ++mt)
#pragma unroll
        for (int nt = 0; nt < 2; ++nt) {
            const int dr = wm + mt * 16 + r;
            const int e0 = wn + nt * 8 + 2 * c;
            L[dr * 65 + e0]           = acc[mt][nt][0];
            L[dr * 65 + e0 + 1]       = acc[mt][nt][1];
            L[(dr + 8) * 65 + e0]     = acc[mt][nt][2];
            L[(dr + 8) * 65 + e0 + 1] = acc[mt][nt][3];
        }
    __syncthreads();

    if (t < 64) {
        const float inva = 1.0f / alpha[h];
        float mx = -1e30f;
        for (int e = 0; e < 64; ++e)
            mx = fmaxf(mx, L[t * 65 + e] * inva);
        float sum = 0.f;
        float* P = g_attnP + (size_t)bh * (kD * kD) + t * kD;
        for (int e = 0; e < 64; ++e) {
            const float ex = expf(L[t * 65 + e] * inva - mx);
            L[t * 65 + e] = ex;
            sum += ex;
        }
        const float inv = 1.0f / sum;
        for (int e = 0; e < 64; ++e)
            P[e] = L[t * 65 + e] * inv;
    }
}

// ---------------------------------------------------------------------------
// U on tensor cores: Ut_b[ct*64+c, h*64+d] = sum_e Wv[h*64+e, ct*64+c] P[d,e]
// NT mma 64x64x64 per block; grid (16 ctiles, 64 bh). 3-term.
// ---------------------------------------------------------------------------
__global__ __launch_bounds__(256)
void u_mma()
{
    __shared__ unsigned AH[32][72], AL[32][72];   // Wv^T planes [e_pair][c]
    __shared__ unsigned BH[32][72], BL[32][72];   // P planes    [e_pair][d]

    const int t = threadIdx.x;
    const int warp = t >> 5, lane = t & 31;
    const int wm = (warp & 1) * 32;       // c
    const int wn = (warp >> 1) * 16;      // d
    const int r = lane >> 2, c4 = lane & 3;
    const int ct = blockIdx.x;            // c tile 0..15
    const int bh = blockIdx.y;
    const int b = bh >> 4, h = bh & 15;

    // stage A = Wv^T (operands already split in gmem; coalesced along c)
    const __half* WvH = g_wqkvH + (size_t)(2048 + h * 64) * kC + ct * 64;
    const __half* WvL = g_wqkvL + (size_t)(2048 + h * 64) * kC + ct * 64;
#pragma unroll
    for (int i = 0; i < 8; ++i) {
        const int idx = t + 256 * i;      // 0..2047
        const int pr = idx >> 6;          // e pair 0..31
        const int cc = idx & 63;
        __half2 hv(WvH[(size_t)(2 * pr) * kC + cc],
                   WvH[(size_t)(2 * pr + 1) * kC + cc]);
        AH[pr][cc] = *(unsigned*)&hv;
        __half2 lv(WvL[(size_t)(2 * pr) * kC + cc],
                   WvL[(size_t)(2 * pr + 1) * kC + cc]);
        AL[pr][cc] = *(unsigned*)&lv;
    }
    // stage B = P (fp32 -> split; k-major already)
    const float* Pg = g_attnP + (size_t)bh * (kD * kD);
#pragma unroll
    for (int i = 0; i < 4; ++i) {
        const int f = t + i * 256;
        const int row = f >> 4;           // d
        const int e4 = (f & 15) * 4;
        const int kp = e4 >> 1;
        float4 p = *(const float4*)(Pg + row * kD + e4);
        split2pack_h(p.x, p.y, BH[kp][row], BL[kp][row]);
        split2pack_h(p.z, p.w, BH[kp + 1][row], BL[kp + 1][row]);
    }
    __syncthreads();

    float acc[2][2][4];
#pragma unroll
    for (int i = 0; i < 2; ++i)
#pragma unroll
        for (int j = 0; j < 2; ++j)
#pragma unroll
            for (int q = 0; q < 4; ++q) acc[i][j][q] = 0.f;

#pragma unroll
    for (int s = 0; s < 4; ++s) {
        const int base = 8 * s;
        unsigned aH[2][4], aL[2][4], bH[2][2], bL[2][2];
#pragma unroll
        for (int mt = 0; mt < 2; ++mt) {
            const int mr = wm + mt * 16 + r;
            aH[mt][0] = AH[base + c4][mr];     aH[mt][1] = AH[base + c4][mr + 8];
            aH[mt][2] = AH[base + c4 + 4][mr]; aH[mt][3] = AH[base + c4 + 4][mr + 8];
            aL[mt][0] = AL[base + c4][mr];     aL[mt][1] = AL[base + c4][mr + 8];
            aL[mt][2] = AL[base + c4 + 4][mr]; aL[mt][3] = AL[base + c4 + 4][mr + 8];
        }
#pragma unroll
        for (int nt = 0; nt < 2; ++nt) {
            const int nr = wn + nt * 8 + r;
            bH[nt][0] = BH[base + c4][nr]; bH[nt][1] = BH[base + c4 + 4][nr];
            bL[nt][0] = BL[base + c4][nr]; bL[nt][1] = BL[base + c4 + 4][nr];
        }
#pragma unroll
        for (int mt = 0; mt < 2; ++mt)
#pragma unroll
            for (int nt = 0; nt < 2; ++nt) {
                mma_f16_f32(acc[mt][nt][0], acc[mt][nt][1], acc[mt][nt][2], acc[mt][nt][3],
                            aH[mt][0], aH[mt][1], aH[mt][2], aH[mt][3], bL[nt][0], bL[nt][1]);
                mma_f16_f32(acc[mt][nt][0], acc[mt][nt][1], acc[mt][nt][2], acc[mt][nt][3],
                            aL[mt][0], aL[mt][1], aL[mt][2], aL[mt][3], bH[nt][0], bH[nt][1]);
                mma_f16_f32(acc[mt][nt][0], acc[mt][nt][1], acc[mt][nt][2], acc[mt][nt][3],
                            aH[mt][0], aH[mt][1], aH[mt][2], aH[mt][3], bH[nt][0], bH[nt][1]);
            }
    }

    // epilogue: Ut[b][ct*64 + c][h*64 + d] split fp16
#pragma unroll
    for (int mt = 0; mt < 2; ++mt) {
#pragma unroll
        for (int nt = 0; nt < 2; ++nt) {
            const int crow = wm + mt * 16 + r;
            const int d0 = wn + nt * 8 + 2 * c4;       // even
            const size_t o0 = (((size_t)b * kC + ct * 64 + crow) * kC
                               + h * 64 + d0) >> 1;
            const size_t o1 = (((size_t)b * kC + ct * 64 + crow + 8) * kC
                               + h * 64 + d0) >> 1;
            unsigned hw, lw;
            split2pack_h(acc[mt][nt][0], acc[mt][nt][1], hw, lw);
            ((unsigned*)g_UtH)[o0] = hw;
            ((unsigned*)g_UtL)[o0] = lw;
            split2pack_h(acc[mt][nt][2], acc[mt][nt][3], hw, lw);
            ((unsigned*)g_UtH)[o1] = hw;
            ((unsigned*)g_UtL)[o1] = lw;
        }
    }
}

// ---------------------------------------------------------------------------
extern "C" void kernel_launch(void* const* d_in, const int* in_sizes, int n_in,
                              void* d_out, int out_size)
{
    const float* x = nullptr;
    const float* Wqkv = nullptr;
    const float* Wproj = nullptr;
    const float* bproj = nullptr;
    const float* alpha = nullptr;
    for (int i = 0; i < n_in; ++i) {
        switch (in_sizes[i]) {
            case kM * kC:    x     = (const float*)d_in[i]; break;
            case kQKV * kC:  Wqkv  = (const float*)d_in[i]; break;
            case kC * kC:    Wproj = (const float*)d_in[i]; break;
            case kC:         bproj = (const float*)d_in[i]; break;
            case kH:         alpha = (const float*)d_in[i]; break;
            default: break;
        }
    }

    __half *xH, *xL, *wqH, *wqL, *wpH, *wpL, *gH, *gL, *tH, *tL;
    __half *utH, *utL, *w2H, *w2L;
    cudaGetSymbolAddress((void**)&xH, g_xH);     cudaGetSymbolAddress((void**)&xL, g_xL);
    cudaGetSymbolAddress((void**)&wqH, g_wqkvH); cudaGetSymbolAddress((void**)&wqL, g_wqkvL);
    cudaGetSymbolAddress((void**)&wpH, g_wprojH); cudaGetSymbolAddress((void**)&wpL, g_wprojL);
    cudaGetSymbolAddress((void**)&gH, g_GH);     cudaGetSymbolAddress((void**)&gL, g_GL);
    cudaGetSymbolAddress((void**)&tH, g_TH);     cudaGetSymbolAddress((void**)&tL, g_TL);
    cudaGetSymbolAddress((void**)&utH, g_UtH);   cudaGetSymbolAddress((void**)&utL, g_UtL);
    cudaGetSymbolAddress((void**)&w2H, g_W2H);   cudaGetSymbolAddress((void**)&w2L, g_W2L);

    cudaFuncSetAttribute(f16_gemm<0, 2>, cudaFuncAttributeMaxDynamicSharedMemorySize, SMEM_GEMM);
    cudaFuncSetAttribute(f16_gemm<2, 3>, cudaFuncAttributeMaxDynamicSharedMemorySize, SMEM_GEMM);
    cudaFuncSetAttribute(gram_gemm,      cudaFuncAttributeMaxDynamicSharedMemorySize, SMEM_GEMM);

    // 0) splits + transpose-split
    {
        int n4 = kM * kC / 4;
        split_kernel<<<(n4 + 255) / 256, 256>>>(x, xH, xL, n4);
        n4 = kQKV * kC / 4;
        split_kernel<<<(n4 + 255) / 256, 256>>>(Wqkv, wqH, wqL, n4);
        n4 = kC * kC / 4;
        split_kernel<<<(n4 + 255) / 256, 256>>>(Wproj, wpH, wpL, n4);
        transpose_split_kernel<<<dim3(kC / 32, kM / 32), 256>>>(x);
    }

    // 1) Gram: G_b = x_b^T x_b (upper-tri + mirror, 3-term)
    gram_gemm<<<dim3(36, 1, kB), 256, SMEM_GEMM>>>();

    // 2) T_b = Wk G_b (3-term, split out)
    f16_gemm<2, 3><<<dim3(kC / 128, kC / 128, kB), 256, SMEM_GEMM>>>(
        wqH + (size_t)1024 * kC, wqL + (size_t)1024 * kC, gH, gL,
        nullptr, nullptr, tH, tL, kC, kC, kC,
        0, (size_t)kC * kC, (size_t)kC * kC);

    // 3) logits = T Wq^T per head + fused softmax -> g_attnP
    logits_softmax<<<kB * kH, 256>>>(alpha);

    // 4) Ut on tensor cores (3-term)
    u_mma<<<dim3(16, kB * kH), 256>>>();

    // 5) W''_b[o,c] = sum_hd Wproj[o,hd] Ut_b[c,hd]  (3-term, split out)
    f16_gemm<2, 3><<<dim3(kC / 128, kC / 128, kB), 256, SMEM_GEMM>>>(
        wpH, wpL, utH, utL,
        nullptr, nullptr, w2H, w2L, kC, kC, kC,
        0, (size_t)kC * kC, (size_t)kC * kC);

    // 6) y_b = x_b W''_b^T + bias  (2-term)
    f16_gemm<0, 2><<<dim3(kC / 128, kN / 128, kB), 256, SMEM_GEMM>>>(
        xH, xL, w2H, w2L,
        (float*)d_out, bproj, nullptr, nullptr, kN, kC, kC,
        (size_t)kN * kC, (size_t)kC * kC, (size_t)kN * kC);
}